// round 1
// baseline (speedup 1.0000x reference)
#include <cuda_runtime.h>
#include <math.h>
#include <stddef.h>

// Problem constants
#define NHEAD 16
#define HDIM  64
#define SEQ   2048
#define BATCH 2
#define EMB   1024
#define MTOT  (BATCH * SEQ)   // 4096

// Scratch (device globals: allocation-free, graph-capturable)
__device__ float g_q[BATCH * NHEAD * SEQ * HDIM];
__device__ float g_k[BATCH * NHEAD * SEQ * HDIM];
__device__ float g_v[BATCH * NHEAD * SEQ * HDIM];
__device__ float g_o[BATCH * SEQ * EMB];

// ---------------------------------------------------------------------------
// GEMM: C[M,N] = A[M,K] @ W[N,K]^T + bias,  M=4096, N=1024, K=1024
// BM=BN=64, BK=16, 256 threads, 4x4 micro-tile per thread.
// writeQKV=1 -> scatter into [b, h, s, d] layout for attention.
// ---------------------------------------------------------------------------
#define GBK  16
#define SPAD 68   // padded row stride (keeps float4 alignment: 68*4 = 272 = 17*16)

__global__ __launch_bounds__(256) void gemm_bias(
    const float* __restrict__ A, const float* __restrict__ W,
    const float* __restrict__ bias, float* __restrict__ C, int writeQKV)
{
    __shared__ float As[GBK][SPAD];  // [k][m]
    __shared__ float Bs[GBK][SPAD];  // [k][n]

    const int tid = threadIdx.x;
    const int tx = tid & 15;        // 0..15  (n sub-tile)
    const int ty = tid >> 4;        // 0..15  (m sub-tile)
    const int m0 = blockIdx.y * 64;
    const int n0 = blockIdx.x * 64;

    const int lr = tid >> 2;        // 0..63 row within tile
    const int lc = (tid & 3) << 2;  // 0,4,8,12 k offset (float4)

    const float* Ap = A + (size_t)(m0 + lr) * EMB + lc;
    const float* Wp = W + (size_t)(n0 + lr) * EMB + lc;

    float acc[4][4];
#pragma unroll
    for (int i = 0; i < 4; i++)
#pragma unroll
        for (int j = 0; j < 4; j++) acc[i][j] = 0.f;

    for (int kk = 0; kk < EMB; kk += GBK) {
        const float4 av = *(const float4*)(Ap + kk);
        const float4 wv = *(const float4*)(Wp + kk);
        __syncthreads();  // previous compute done before overwrite
        As[lc + 0][lr] = av.x; As[lc + 1][lr] = av.y;
        As[lc + 2][lr] = av.z; As[lc + 3][lr] = av.w;
        Bs[lc + 0][lr] = wv.x; Bs[lc + 1][lr] = wv.y;
        Bs[lc + 2][lr] = wv.z; Bs[lc + 3][lr] = wv.w;
        __syncthreads();
#pragma unroll
        for (int k = 0; k < GBK; k++) {
            const float4 a4 = *(const float4*)&As[k][ty << 2];
            const float4 b4 = *(const float4*)&Bs[k][tx << 2];
            const float ar[4] = {a4.x, a4.y, a4.z, a4.w};
            const float br[4] = {b4.x, b4.y, b4.z, b4.w};
#pragma unroll
            for (int i = 0; i < 4; i++)
#pragma unroll
                for (int j = 0; j < 4; j++)
                    acc[i][j] = fmaf(ar[i], br[j], acc[i][j]);
        }
    }

#pragma unroll
    for (int i = 0; i < 4; i++) {
        const int m = m0 + (ty << 2) + i;
#pragma unroll
        for (int j = 0; j < 4; j++) {
            const int n = n0 + (tx << 2) + j;
            const float v = acc[i][j] + bias[n];
            if (writeQKV) {
                const int b = m >> 11;          // m / SEQ
                const int s = m & (SEQ - 1);
                const int h = n >> 6;           // n / HDIM
                const int d = n & 63;
                C[(((size_t)(b * NHEAD + h)) * SEQ + s) * HDIM + d] = v;
            } else {
                C[(size_t)m * EMB + n] = v;
            }
        }
    }
}

// ---------------------------------------------------------------------------
// Causal flash attention: per (b*h, q-block of 64). 64-key tiles, D=64.
// 256 threads, 4x4 micro-tiles for both S=QK^T and O=PV.
// ---------------------------------------------------------------------------
#define ATT_SMEM_BYTES (4 * 64 * SPAD * 4)   // Qs + Ks + Vs + Ps = 69632 B

__global__ __launch_bounds__(256) void attn_kernel(
    const float* __restrict__ Q, const float* __restrict__ K,
    const float* __restrict__ V, float* __restrict__ O)
{
    extern __shared__ float sh[];
    float (*Qs)[SPAD] = (float (*)[SPAD])(sh);               // [d][q]
    float (*Ks)[SPAD] = (float (*)[SPAD])(sh + 64 * SPAD);   // [d][k]
    float (*Vs)[SPAD] = (float (*)[SPAD])(sh + 2 * 64 * SPAD); // [k][d]
    float (*Ps)[SPAD] = (float (*)[SPAD])(sh + 3 * 64 * SPAD); // [q][k]

    const int tid = threadIdx.x;
    const int tx = tid & 15;   // key / dim sub-tile
    const int ty = tid >> 4;   // query sub-tile
    const int bh = blockIdx.y; // b * NHEAD + h
    const int qb = blockIdx.x; // query block

    const float* Qb = Q + ((size_t)bh * SEQ + (size_t)qb * 64) * HDIM;
    const float* Kb = K + (size_t)bh * SEQ * HDIM;
    const float* Vb = V + (size_t)bh * SEQ * HDIM;

    const int lr = tid >> 2;        // 0..63 (row within 64-row tile)
    const int lc = (tid & 3) << 4;  // 0,16,32,48 (16 floats per thread)

    // Load Q transposed: Qs[d][q]
#pragma unroll
    for (int u = 0; u < 4; u++) {
        const float4 qv = *(const float4*)(Qb + (size_t)lr * HDIM + lc + u * 4);
        Qs[lc + u * 4 + 0][lr] = qv.x;
        Qs[lc + u * 4 + 1][lr] = qv.y;
        Qs[lc + u * 4 + 2][lr] = qv.z;
        Qs[lc + u * 4 + 3][lr] = qv.w;
    }

    float m_i[4], l_i[4], o_acc[4][4];
#pragma unroll
    for (int i = 0; i < 4; i++) {
        m_i[i] = -INFINITY;
        l_i[i] = 0.f;
#pragma unroll
        for (int j = 0; j < 4; j++) o_acc[i][j] = 0.f;
    }

    for (int jb = 0; jb <= qb; jb++) {
        __syncthreads();  // prior PV (and initial Q stores) done before overwrite
        const float* Kt = Kb + (size_t)jb * 64 * HDIM;
        const float* Vt = Vb + (size_t)jb * 64 * HDIM;
#pragma unroll
        for (int u = 0; u < 4; u++) {
            const float4 kv = *(const float4*)(Kt + (size_t)lr * HDIM + lc + u * 4);
            Ks[lc + u * 4 + 0][lr] = kv.x;
            Ks[lc + u * 4 + 1][lr] = kv.y;
            Ks[lc + u * 4 + 2][lr] = kv.z;
            Ks[lc + u * 4 + 3][lr] = kv.w;
            const float4 vv = *(const float4*)(Vt + (size_t)lr * HDIM + lc + u * 4);
            *(float4*)&Vs[lr][lc + u * 4] = vv;
        }
        __syncthreads();

        // S = Q @ K^T
        float s[4][4];
#pragma unroll
        for (int i = 0; i < 4; i++)
#pragma unroll
            for (int j = 0; j < 4; j++) s[i][j] = 0.f;
#pragma unroll 16
        for (int d = 0; d < HDIM; d++) {
            const float4 a4 = *(const float4*)&Qs[d][ty << 2];
            const float4 b4 = *(const float4*)&Ks[d][tx << 2];
            const float ar[4] = {a4.x, a4.y, a4.z, a4.w};
            const float br[4] = {b4.x, b4.y, b4.z, b4.w};
#pragma unroll
            for (int i = 0; i < 4; i++)
#pragma unroll
                for (int j = 0; j < 4; j++)
                    s[i][j] = fmaf(ar[i], br[j], s[i][j]);
        }

        // scale + causal mask (only the diagonal block is partially masked)
        const bool diag = (jb == qb);
#pragma unroll
        for (int i = 0; i < 4; i++)
#pragma unroll
            for (int j = 0; j < 4; j++) {
                s[i][j] *= 0.125f;  // 1/sqrt(64)
                if (diag && ((tx << 2) + j) > ((ty << 2) + i)) s[i][j] = -INFINITY;
            }

        // Online softmax (rows spread across 16-lane groups)
        float corr[4];
#pragma unroll
        for (int i = 0; i < 4; i++) {
            float rm = fmaxf(fmaxf(s[i][0], s[i][1]), fmaxf(s[i][2], s[i][3]));
#pragma unroll
            for (int off = 8; off > 0; off >>= 1)
                rm = fmaxf(rm, __shfl_xor_sync(0xffffffffu, rm, off, 16));
            const float mn = fmaxf(m_i[i], rm);
            corr[i] = __expf(m_i[i] - mn);
            m_i[i] = mn;
            float rs = 0.f;
#pragma unroll
            for (int j = 0; j < 4; j++) {
                s[i][j] = __expf(s[i][j] - mn);
                rs += s[i][j];
            }
#pragma unroll
            for (int off = 8; off > 0; off >>= 1)
                rs += __shfl_xor_sync(0xffffffffu, rs, off, 16);
            l_i[i] = l_i[i] * corr[i] + rs;
        }

        // store P, rescale O accumulators
#pragma unroll
        for (int i = 0; i < 4; i++) {
            *(float4*)&Ps[(ty << 2) + i][tx << 2] =
                make_float4(s[i][0], s[i][1], s[i][2], s[i][3]);
#pragma unroll
            for (int j = 0; j < 4; j++) o_acc[i][j] *= corr[i];
        }
        __syncthreads();

        // O += P @ V
#pragma unroll 16
        for (int kk = 0; kk < 64; kk++) {
            const float4 v4 = *(const float4*)&Vs[kk][tx << 2];
            const float vr[4] = {v4.x, v4.y, v4.z, v4.w};
            const float pr[4] = {Ps[(ty << 2) + 0][kk], Ps[(ty << 2) + 1][kk],
                                 Ps[(ty << 2) + 2][kk], Ps[(ty << 2) + 3][kk]};
#pragma unroll
            for (int i = 0; i < 4; i++)
#pragma unroll
                for (int j = 0; j < 4; j++)
                    o_acc[i][j] = fmaf(pr[i], vr[j], o_acc[i][j]);
        }
    }

    // Epilogue: normalize and write to [b, s, h*D + d] layout
    const int b = bh >> 4;
    const int h = bh & 15;
#pragma unroll
    for (int i = 0; i < 4; i++) {
        const float inv = 1.f / l_i[i];
        const int srow = qb * 64 + (ty << 2) + i;
        float* op = O + ((size_t)(b * SEQ + srow)) * EMB + h * HDIM + (tx << 2);
        float4 ov;
        ov.x = o_acc[i][0] * inv;
        ov.y = o_acc[i][1] * inv;
        ov.z = o_acc[i][2] * inv;
        ov.w = o_acc[i][3] * inv;
        *(float4*)op = ov;
    }
}

// ---------------------------------------------------------------------------
extern "C" void kernel_launch(void* const* d_in, const int* in_sizes, int n_in,
                              void* d_out, int out_size)
{
    (void)in_sizes; (void)n_in; (void)out_size;
    const float* x  = (const float*)d_in[0];
    // d_in[1] = mask (causal tril, implied — unused)
    const float* Wq = (const float*)d_in[2];
    const float* bq = (const float*)d_in[3];
    const float* Wk = (const float*)d_in[4];
    const float* bk = (const float*)d_in[5];
    const float* Wv = (const float*)d_in[6];
    const float* bv = (const float*)d_in[7];
    const float* Wo = (const float*)d_in[8];
    const float* bo = (const float*)d_in[9];
    float* out = (float*)d_out;

    float *gq, *gk, *gv, *go;
    cudaGetSymbolAddress((void**)&gq, g_q);
    cudaGetSymbolAddress((void**)&gk, g_k);
    cudaGetSymbolAddress((void**)&gv, g_v);
    cudaGetSymbolAddress((void**)&go, g_o);

    cudaFuncSetAttribute(attn_kernel, cudaFuncAttributeMaxDynamicSharedMemorySize,
                         ATT_SMEM_BYTES);

    const dim3 gemm_grid(EMB / 64, MTOT / 64);  // (16, 64)
    gemm_bias<<<gemm_grid, 256>>>(x, Wq, bq, gq, 1);
    gemm_bias<<<gemm_grid, 256>>>(x, Wk, bk, gk, 1);
    gemm_bias<<<gemm_grid, 256>>>(x, Wv, bv, gv, 1);

    const dim3 attn_grid(SEQ / 64, BATCH * NHEAD);  // (32, 32)
    attn_kernel<<<attn_grid, 256, ATT_SMEM_BYTES>>>(gq, gk, gv, go);

    gemm_bias<<<gemm_grid, 256>>>(go, Wo, bo, out, 0);
}

// round 4
// speedup vs baseline: 1.6460x; 1.6460x over previous
#include <cuda_runtime.h>
#include <cuda_bf16.h>
#include <math.h>
#include <stddef.h>
#include <stdint.h>

// Problem constants
#define NHEAD 16
#define HDIM  64
#define SEQ   2048
#define BATCH 2
#define EMB   1024
#define MTOT  (BATCH * SEQ)   // 4096

// Scratch (device globals: allocation-free, graph-capturable)
__device__ float g_q[BATCH * NHEAD * SEQ * HDIM];
__device__ float g_k[BATCH * NHEAD * SEQ * HDIM];
__device__ float g_v[BATCH * NHEAD * SEQ * HDIM];
__device__ float g_o[BATCH * SEQ * EMB];

// ===========================================================================
// mma.sync helpers (arch-portable tensor core path; works at compute_103)
// ===========================================================================
__device__ __forceinline__ void mma_bf16(float* d, const uint32_t* a, const uint32_t* b) {
    asm volatile(
        "mma.sync.aligned.m16n8k16.row.col.f32.bf16.bf16.f32 "
        "{%0,%1,%2,%3}, {%4,%5,%6,%7}, {%8,%9}, {%0,%1,%2,%3};"
        : "+f"(d[0]), "+f"(d[1]), "+f"(d[2]), "+f"(d[3])
        : "r"(a[0]), "r"(a[1]), "r"(a[2]), "r"(a[3]), "r"(b[0]), "r"(b[1]));
}

__device__ __forceinline__ void ldsm4(uint32_t* r, uint32_t addr) {
    asm volatile("ldmatrix.sync.aligned.m8n8.x4.shared.b16 {%0,%1,%2,%3}, [%4];"
        : "=r"(r[0]), "=r"(r[1]), "=r"(r[2]), "=r"(r[3]) : "r"(addr));
}

__device__ __forceinline__ uint32_t smem_u32(const void* p) {
    uint32_t a;
    asm("{ .reg .u64 t; cvta.to.shared.u64 t, %1; cvt.u32.u64 %0, t; }"
        : "=r"(a) : "l"(p));
    return a;
}

// hi/lo bf16 split of 2 floats (packed into u32 each)
__device__ __forceinline__ void split2(float x, float y, uint32_t& hi, uint32_t& lo) {
    __nv_bfloat162 h = __floats2bfloat162_rn(x, y);
    float hx = __bfloat162float(h.x), hy = __bfloat162float(h.y);
    __nv_bfloat162 l = __floats2bfloat162_rn(x - hx, y - hy);
    hi = *(uint32_t*)&h;
    lo = *(uint32_t*)&l;
}

// ===========================================================================
// Tensor-core GEMM: C[M,N] = A[M,K] @ W[N,K]^T + bias (M=4096, N=1024, K=1024)
// CTA 128x128, BK=32, 8 warps (4x2), warp tile 32x64, m16n8k16 bf16 hi/lo split.
// Smem row stride 80B: 16B-aligned for LDSM (fixes round-3 fault) and
// conflict-free (row offsets mod 128 cover all banks once).
// ===========================================================================
#define GBK 32
#define SROWB 80                       // bytes per smem row (32 bf16 data + pad)
#define SROWW (SROWB / 4)              // 20 u32 words
#define TILE_U32 (128 * SROWW)         // 2560 words per tile buffer

__global__ __launch_bounds__(256, 1) void gemm_tc(
    const float* __restrict__ A, const float* __restrict__ W,
    const float* __restrict__ bias, float* __restrict__ C, int writeQKV)
{
    __shared__ uint32_t sh[4 * TILE_U32];   // 40960 B: Ah, Al, Bh, Bl
    uint32_t* Ah = sh;
    uint32_t* Al = sh + TILE_U32;
    uint32_t* Bh = sh + 2 * TILE_U32;
    uint32_t* Bl = sh + 3 * TILE_U32;

    const int tid = threadIdx.x;
    const int lane = tid & 31;
    const int wid = tid >> 5;
    const int wm = wid & 3;       // 0..3 -> 32 m-rows each
    const int wn = wid >> 2;      // 0..1 -> 64 n-cols each
    const int m0 = blockIdx.y * 128;
    const int n0 = blockIdx.x * 128;

    // gmem staging: each thread loads 4 float4 per matrix per chunk
    const int grow = tid >> 3;          // base row (0..31); rows step by 32
    const int gc4 = (tid & 7) << 2;     // float offset within 32-wide chunk
    const int kp = (tid & 7) << 1;      // u32 word offset within smem row

    // ldmatrix source addresses (byte offsets; row stride 80B, all 16B-aligned)
    const int mat = lane >> 3, lr8 = lane & 7;
    const uint32_t sbase = smem_u32(sh);
    // A matrices 0..3 = {m0k0, m8k0, m0k8, m8k8}
    const uint32_t a_off = (uint32_t)((wm * 32 + (mat & 1) * 8 + lr8) * SROWB + (mat >> 1) * 16);
    // B matrices 0..3 = {n0k0, n0k8, n8k0, n8k8}
    const uint32_t b_off = (uint32_t)((wn * 64 + (mat >> 1) * 8 + lr8) * SROWB + (mat & 1) * 16);

    const uint32_t sAh = sbase + a_off;
    const uint32_t sAl = sAh + TILE_U32 * 4;
    const uint32_t sBh = sbase + 2 * TILE_U32 * 4 + b_off;
    const uint32_t sBl = sBh + TILE_U32 * 4;

    float acc[2][8][4];
#pragma unroll
    for (int mf = 0; mf < 2; mf++)
#pragma unroll
        for (int nf = 0; nf < 8; nf++)
#pragma unroll
            for (int e = 0; e < 4; e++) acc[mf][nf][e] = 0.f;

    const float* Ag = A + (size_t)m0 * EMB;
    const float* Wg = W + (size_t)n0 * EMB;

    float4 avr[4], wvr[4];
#pragma unroll
    for (int u = 0; u < 4; u++) {
        avr[u] = *(const float4*)(Ag + (size_t)(grow + u * 32) * EMB + gc4);
        wvr[u] = *(const float4*)(Wg + (size_t)(grow + u * 32) * EMB + gc4);
    }

    for (int kk = 0; kk < EMB / GBK; kk++) {
        __syncthreads();   // previous chunk's compute done before smem overwrite
#pragma unroll
        for (int u = 0; u < 4; u++) {
            const int row = grow + u * 32;
            const int w0 = row * SROWW + kp;
            uint32_t h0, l0, h1, l1;
            split2(avr[u].x, avr[u].y, h0, l0);
            split2(avr[u].z, avr[u].w, h1, l1);
            *(uint2*)(Ah + w0) = make_uint2(h0, h1);
            *(uint2*)(Al + w0) = make_uint2(l0, l1);
            split2(wvr[u].x, wvr[u].y, h0, l0);
            split2(wvr[u].z, wvr[u].w, h1, l1);
            *(uint2*)(Bh + w0) = make_uint2(h0, h1);
            *(uint2*)(Bl + w0) = make_uint2(l0, l1);
        }
        __syncthreads();

        // prefetch next chunk (overlaps with MMA below)
        if (kk + 1 < EMB / GBK) {
            const int kcol = (kk + 1) * GBK + gc4;
#pragma unroll
            for (int u = 0; u < 4; u++) {
                avr[u] = *(const float4*)(Ag + (size_t)(grow + u * 32) * EMB + kcol);
                wvr[u] = *(const float4*)(Wg + (size_t)(grow + u * 32) * EMB + kcol);
            }
        }

#pragma unroll
        for (int ks = 0; ks < 2; ks++) {
            const uint32_t kadd = ks * 32;   // 16 bf16 = 32 bytes
            uint32_t ah[2][4], al[2][4], bh[4][4], bl[4][4];
#pragma unroll
            for (int mf = 0; mf < 2; mf++) {
                ldsm4(ah[mf], sAh + mf * 16 * SROWB + kadd);
                ldsm4(al[mf], sAl + mf * 16 * SROWB + kadd);
            }
#pragma unroll
            for (int np = 0; np < 4; np++) {
                ldsm4(bh[np], sBh + np * 16 * SROWB + kadd);
                ldsm4(bl[np], sBl + np * 16 * SROWB + kadd);
            }
#pragma unroll
            for (int mf = 0; mf < 2; mf++)
#pragma unroll
                for (int nf = 0; nf < 8; nf++) {
                    const int np = nf >> 1;
                    uint32_t* bhp = &bh[np][(nf & 1) * 2];
                    uint32_t* blp = &bl[np][(nf & 1) * 2];
                    mma_bf16(acc[mf][nf], ah[mf], bhp);
                    mma_bf16(acc[mf][nf], ah[mf], blp);
                    mma_bf16(acc[mf][nf], al[mf], bhp);
                }
        }
    }

    // Epilogue: bias + write (optionally scatter to [b,h,s,d])
#pragma unroll
    for (int mf = 0; mf < 2; mf++) {
#pragma unroll
        for (int half = 0; half < 2; half++) {
            const int m = m0 + wm * 32 + mf * 16 + (lane >> 2) + half * 8;
            const int b = m >> 11;
            const int s = m & (SEQ - 1);
#pragma unroll
            for (int nf = 0; nf < 8; nf++) {
                const int n = n0 + wn * 64 + nf * 8 + ((lane & 3) << 1);
                float2 v;
                v.x = acc[mf][nf][half * 2 + 0] + bias[n];
                v.y = acc[mf][nf][half * 2 + 1] + bias[n + 1];
                if (writeQKV) {
                    const int h = n >> 6;
                    const int d = n & 63;
                    *(float2*)(C + (((size_t)(b * NHEAD + h)) * SEQ + s) * HDIM + d) = v;
                } else {
                    *(float2*)(C + (size_t)m * EMB + n) = v;
                }
            }
        }
    }
}

// ---------------------------------------------------------------------------
// Causal flash attention: per (b*h, q-block of 64). 64-key tiles, D=64.
// 256 threads, 4x4 micro-tiles. (unchanged from round-1 passing version)
// ---------------------------------------------------------------------------
#define SPAD 68
#define ATT_SMEM_BYTES (4 * 64 * SPAD * 4)   // 69632 B

__global__ __launch_bounds__(256) void attn_kernel(
    const float* __restrict__ Q, const float* __restrict__ K,
    const float* __restrict__ V, float* __restrict__ O)
{
    extern __shared__ float sh[];
    float (*Qs)[SPAD] = (float (*)[SPAD])(sh);                 // [d][q]
    float (*Ks)[SPAD] = (float (*)[SPAD])(sh + 64 * SPAD);     // [d][k]
    float (*Vs)[SPAD] = (float (*)[SPAD])(sh + 2 * 64 * SPAD); // [k][d]
    float (*Ps)[SPAD] = (float (*)[SPAD])(sh + 3 * 64 * SPAD); // [q][k]

    const int tid = threadIdx.x;
    const int tx = tid & 15;
    const int ty = tid >> 4;
    const int bh = blockIdx.y;
    const int qb = blockIdx.x;

    const float* Qb = Q + ((size_t)bh * SEQ + (size_t)qb * 64) * HDIM;
    const float* Kb = K + (size_t)bh * SEQ * HDIM;
    const float* Vb = V + (size_t)bh * SEQ * HDIM;

    const int lr = tid >> 2;
    const int lc = (tid & 3) << 4;

#pragma unroll
    for (int u = 0; u < 4; u++) {
        const float4 qv = *(const float4*)(Qb + (size_t)lr * HDIM + lc + u * 4);
        Qs[lc + u * 4 + 0][lr] = qv.x;
        Qs[lc + u * 4 + 1][lr] = qv.y;
        Qs[lc + u * 4 + 2][lr] = qv.z;
        Qs[lc + u * 4 + 3][lr] = qv.w;
    }

    float m_i[4], l_i[4], o_acc[4][4];
#pragma unroll
    for (int i = 0; i < 4; i++) {
        m_i[i] = -INFINITY;
        l_i[i] = 0.f;
#pragma unroll
        for (int j = 0; j < 4; j++) o_acc[i][j] = 0.f;
    }

    for (int jb = 0; jb <= qb; jb++) {
        __syncthreads();
        const float* Kt = Kb + (size_t)jb * 64 * HDIM;
        const float* Vt = Vb + (size_t)jb * 64 * HDIM;
#pragma unroll
        for (int u = 0; u < 4; u++) {
            const float4 kv = *(const float4*)(Kt + (size_t)lr * HDIM + lc + u * 4);
            Ks[lc + u * 4 + 0][lr] = kv.x;
            Ks[lc + u * 4 + 1][lr] = kv.y;
            Ks[lc + u * 4 + 2][lr] = kv.z;
            Ks[lc + u * 4 + 3][lr] = kv.w;
            const float4 vv = *(const float4*)(Vt + (size_t)lr * HDIM + lc + u * 4);
            *(float4*)&Vs[lr][lc + u * 4] = vv;
        }
        __syncthreads();

        float s[4][4];
#pragma unroll
        for (int i = 0; i < 4; i++)
#pragma unroll
            for (int j = 0; j < 4; j++) s[i][j] = 0.f;
#pragma unroll 16
        for (int d = 0; d < HDIM; d++) {
            const float4 a4 = *(const float4*)&Qs[d][ty << 2];
            const float4 b4 = *(const float4*)&Ks[d][tx << 2];
            const float ar[4] = {a4.x, a4.y, a4.z, a4.w};
            const float br[4] = {b4.x, b4.y, b4.z, b4.w};
#pragma unroll
            for (int i = 0; i < 4; i++)
#pragma unroll
                for (int j = 0; j < 4; j++)
                    s[i][j] = fmaf(ar[i], br[j], s[i][j]);
        }

        const bool diag = (jb == qb);
#pragma unroll
        for (int i = 0; i < 4; i++)
#pragma unroll
            for (int j = 0; j < 4; j++) {
                s[i][j] *= 0.125f;
                if (diag && ((tx << 2) + j) > ((ty << 2) + i)) s[i][j] = -INFINITY;
            }

        float corr[4];
#pragma unroll
        for (int i = 0; i < 4; i++) {
            float rm = fmaxf(fmaxf(s[i][0], s[i][1]), fmaxf(s[i][2], s[i][3]));
#pragma unroll
            for (int off = 8; off > 0; off >>= 1)
                rm = fmaxf(rm, __shfl_xor_sync(0xffffffffu, rm, off, 16));
            const float mn = fmaxf(m_i[i], rm);
            corr[i] = __expf(m_i[i] - mn);
            m_i[i] = mn;
            float rs = 0.f;
#pragma unroll
            for (int j = 0; j < 4; j++) {
                s[i][j] = __expf(s[i][j] - mn);
                rs += s[i][j];
            }
#pragma unroll
            for (int off = 8; off > 0; off >>= 1)
                rs += __shfl_xor_sync(0xffffffffu, rs, off, 16);
            l_i[i] = l_i[i] * corr[i] + rs;
        }

#pragma unroll
        for (int i = 0; i < 4; i++) {
            *(float4*)&Ps[(ty << 2) + i][tx << 2] =
                make_float4(s[i][0], s[i][1], s[i][2], s[i][3]);
#pragma unroll
            for (int j = 0; j < 4; j++) o_acc[i][j] *= corr[i];
        }
        __syncthreads();

#pragma unroll 16
        for (int kkk = 0; kkk < 64; kkk++) {
            const float4 v4 = *(const float4*)&Vs[kkk][tx << 2];
            const float vr[4] = {v4.x, v4.y, v4.z, v4.w};
            const float pr[4] = {Ps[(ty << 2) + 0][kkk], Ps[(ty << 2) + 1][kkk],
                                 Ps[(ty << 2) + 2][kkk], Ps[(ty << 2) + 3][kkk]};
#pragma unroll
            for (int i = 0; i < 4; i++)
#pragma unroll
                for (int j = 0; j < 4; j++)
                    o_acc[i][j] = fmaf(pr[i], vr[j], o_acc[i][j]);
        }
    }

    const int b = bh >> 4;
    const int h = bh & 15;
#pragma unroll
    for (int i = 0; i < 4; i++) {
        const float inv = 1.f / l_i[i];
        const int srow = qb * 64 + (ty << 2) + i;
        float* op = O + ((size_t)(b * SEQ + srow)) * EMB + h * HDIM + (tx << 2);
        float4 ov;
        ov.x = o_acc[i][0] * inv;
        ov.y = o_acc[i][1] * inv;
        ov.z = o_acc[i][2] * inv;
        ov.w = o_acc[i][3] * inv;
        *(float4*)op = ov;
    }
}

// ---------------------------------------------------------------------------
extern "C" void kernel_launch(void* const* d_in, const int* in_sizes, int n_in,
                              void* d_out, int out_size)
{
    (void)in_sizes; (void)n_in; (void)out_size;
    const float* x  = (const float*)d_in[0];
    // d_in[1] = mask (causal tril, implied — unused)
    const float* Wq = (const float*)d_in[2];
    const float* bq = (const float*)d_in[3];
    const float* Wk = (const float*)d_in[4];
    const float* bk = (const float*)d_in[5];
    const float* Wv = (const float*)d_in[6];
    const float* bv = (const float*)d_in[7];
    const float* Wo = (const float*)d_in[8];
    const float* bo = (const float*)d_in[9];
    float* out = (float*)d_out;

    float *gq, *gk, *gv, *go;
    cudaGetSymbolAddress((void**)&gq, g_q);
    cudaGetSymbolAddress((void**)&gk, g_k);
    cudaGetSymbolAddress((void**)&gv, g_v);
    cudaGetSymbolAddress((void**)&go, g_o);

    cudaFuncSetAttribute(attn_kernel, cudaFuncAttributeMaxDynamicSharedMemorySize,
                         ATT_SMEM_BYTES);

    const dim3 gemm_grid(EMB / 128, MTOT / 128);  // (8, 32)
    gemm_tc<<<gemm_grid, 256>>>(x, Wq, bq, gq, 1);
    gemm_tc<<<gemm_grid, 256>>>(x, Wk, bk, gk, 1);
    gemm_tc<<<gemm_grid, 256>>>(x, Wv, bv, gv, 1);

    const dim3 attn_grid(SEQ / 64, BATCH * NHEAD);  // (32, 32)
    attn_kernel<<<attn_grid, 256, ATT_SMEM_BYTES>>>(gq, gk, gv, go);

    gemm_tc<<<gemm_grid, 256>>>(go, Wo, bo, out, 0);
}

// round 5
// speedup vs baseline: 3.0215x; 1.8357x over previous
#include <cuda_runtime.h>
#include <cuda_bf16.h>
#include <math.h>
#include <stddef.h>
#include <stdint.h>

// Problem constants
#define NHEAD 16
#define HDIM  64
#define SEQ   2048
#define BATCH 2
#define EMB   1024
#define MTOT  (BATCH * SEQ)   // 4096

// Scratch (device globals: allocation-free, graph-capturable)
__device__ float g_q[BATCH * NHEAD * SEQ * HDIM];
__device__ float g_k[BATCH * NHEAD * SEQ * HDIM];
__device__ float g_v[BATCH * NHEAD * SEQ * HDIM];
__device__ float g_o[BATCH * SEQ * EMB];

// ===========================================================================
// mma.sync helpers (arch-portable tensor core path; works at compute_103)
// ===========================================================================
__device__ __forceinline__ void mma_bf16(float* d, const uint32_t* a, const uint32_t* b) {
    asm volatile(
        "mma.sync.aligned.m16n8k16.row.col.f32.bf16.bf16.f32 "
        "{%0,%1,%2,%3}, {%4,%5,%6,%7}, {%8,%9}, {%0,%1,%2,%3};"
        : "+f"(d[0]), "+f"(d[1]), "+f"(d[2]), "+f"(d[3])
        : "r"(a[0]), "r"(a[1]), "r"(a[2]), "r"(a[3]), "r"(b[0]), "r"(b[1]));
}

__device__ __forceinline__ void ldsm4(uint32_t* r, uint32_t addr) {
    asm volatile("ldmatrix.sync.aligned.m8n8.x4.shared.b16 {%0,%1,%2,%3}, [%4];"
        : "=r"(r[0]), "=r"(r[1]), "=r"(r[2]), "=r"(r[3]) : "r"(addr));
}

__device__ __forceinline__ void ldsm4t(uint32_t* r, uint32_t addr) {
    asm volatile("ldmatrix.sync.aligned.m8n8.x4.trans.shared.b16 {%0,%1,%2,%3}, [%4];"
        : "=r"(r[0]), "=r"(r[1]), "=r"(r[2]), "=r"(r[3]) : "r"(addr));
}

__device__ __forceinline__ uint32_t smem_u32(const void* p) {
    uint32_t a;
    asm("{ .reg .u64 t; cvta.to.shared.u64 t, %1; cvt.u32.u64 %0, t; }"
        : "=r"(a) : "l"(p));
    return a;
}

// hi/lo bf16 split of 2 floats (packed into u32 each)
__device__ __forceinline__ void split2(float x, float y, uint32_t& hi, uint32_t& lo) {
    __nv_bfloat162 h = __floats2bfloat162_rn(x, y);
    float hx = __bfloat162float(h.x), hy = __bfloat162float(h.y);
    __nv_bfloat162 l = __floats2bfloat162_rn(x - hx, y - hy);
    hi = *(uint32_t*)&h;
    lo = *(uint32_t*)&l;
}

// ===========================================================================
// Tensor-core GEMM: C[M,N] = A[M,K] @ W[N,K]^T + bias (unchanged, passing)
// ===========================================================================
#define GBK 32
#define SROWB 80
#define SROWW (SROWB / 4)
#define TILE_U32 (128 * SROWW)

__global__ __launch_bounds__(256, 1) void gemm_tc(
    const float* __restrict__ A, const float* __restrict__ W,
    const float* __restrict__ bias, float* __restrict__ C, int writeQKV)
{
    __shared__ uint32_t sh[4 * TILE_U32];   // 40960 B: Ah, Al, Bh, Bl
    uint32_t* Ah = sh;
    uint32_t* Al = sh + TILE_U32;
    uint32_t* Bh = sh + 2 * TILE_U32;
    uint32_t* Bl = sh + 3 * TILE_U32;

    const int tid = threadIdx.x;
    const int lane = tid & 31;
    const int wid = tid >> 5;
    const int wm = wid & 3;
    const int wn = wid >> 2;
    const int m0 = blockIdx.y * 128;
    const int n0 = blockIdx.x * 128;

    const int grow = tid >> 3;
    const int gc4 = (tid & 7) << 2;
    const int kp = (tid & 7) << 1;

    const int mat = lane >> 3, lr8 = lane & 7;
    const uint32_t sbase = smem_u32(sh);
    const uint32_t a_off = (uint32_t)((wm * 32 + (mat & 1) * 8 + lr8) * SROWB + (mat >> 1) * 16);
    const uint32_t b_off = (uint32_t)((wn * 64 + (mat >> 1) * 8 + lr8) * SROWB + (mat & 1) * 16);

    const uint32_t sAh = sbase + a_off;
    const uint32_t sAl = sAh + TILE_U32 * 4;
    const uint32_t sBh = sbase + 2 * TILE_U32 * 4 + b_off;
    const uint32_t sBl = sBh + TILE_U32 * 4;

    float acc[2][8][4];
#pragma unroll
    for (int mf = 0; mf < 2; mf++)
#pragma unroll
        for (int nf = 0; nf < 8; nf++)
#pragma unroll
            for (int e = 0; e < 4; e++) acc[mf][nf][e] = 0.f;

    const float* Ag = A + (size_t)m0 * EMB;
    const float* Wg = W + (size_t)n0 * EMB;

    float4 avr[4], wvr[4];
#pragma unroll
    for (int u = 0; u < 4; u++) {
        avr[u] = *(const float4*)(Ag + (size_t)(grow + u * 32) * EMB + gc4);
        wvr[u] = *(const float4*)(Wg + (size_t)(grow + u * 32) * EMB + gc4);
    }

    for (int kk = 0; kk < EMB / GBK; kk++) {
        __syncthreads();
#pragma unroll
        for (int u = 0; u < 4; u++) {
            const int row = grow + u * 32;
            const int w0 = row * SROWW + kp;
            uint32_t h0, l0, h1, l1;
            split2(avr[u].x, avr[u].y, h0, l0);
            split2(avr[u].z, avr[u].w, h1, l1);
            *(uint2*)(Ah + w0) = make_uint2(h0, h1);
            *(uint2*)(Al + w0) = make_uint2(l0, l1);
            split2(wvr[u].x, wvr[u].y, h0, l0);
            split2(wvr[u].z, wvr[u].w, h1, l1);
            *(uint2*)(Bh + w0) = make_uint2(h0, h1);
            *(uint2*)(Bl + w0) = make_uint2(l0, l1);
        }
        __syncthreads();

        if (kk + 1 < EMB / GBK) {
            const int kcol = (kk + 1) * GBK + gc4;
#pragma unroll
            for (int u = 0; u < 4; u++) {
                avr[u] = *(const float4*)(Ag + (size_t)(grow + u * 32) * EMB + kcol);
                wvr[u] = *(const float4*)(Wg + (size_t)(grow + u * 32) * EMB + kcol);
            }
        }

#pragma unroll
        for (int ks = 0; ks < 2; ks++) {
            const uint32_t kadd = ks * 32;
            uint32_t ah[2][4], al[2][4], bh[4][4], bl[4][4];
#pragma unroll
            for (int mf = 0; mf < 2; mf++) {
                ldsm4(ah[mf], sAh + mf * 16 * SROWB + kadd);
                ldsm4(al[mf], sAl + mf * 16 * SROWB + kadd);
            }
#pragma unroll
            for (int np = 0; np < 4; np++) {
                ldsm4(bh[np], sBh + np * 16 * SROWB + kadd);
                ldsm4(bl[np], sBl + np * 16 * SROWB + kadd);
            }
#pragma unroll
            for (int mf = 0; mf < 2; mf++)
#pragma unroll
                for (int nf = 0; nf < 8; nf++) {
                    const int np = nf >> 1;
                    uint32_t* bhp = &bh[np][(nf & 1) * 2];
                    uint32_t* blp = &bl[np][(nf & 1) * 2];
                    mma_bf16(acc[mf][nf], ah[mf], bhp);
                    mma_bf16(acc[mf][nf], ah[mf], blp);
                    mma_bf16(acc[mf][nf], al[mf], bhp);
                }
        }
    }

#pragma unroll
    for (int mf = 0; mf < 2; mf++) {
#pragma unroll
        for (int half = 0; half < 2; half++) {
            const int m = m0 + wm * 32 + mf * 16 + (lane >> 2) + half * 8;
            const int b = m >> 11;
            const int s = m & (SEQ - 1);
#pragma unroll
            for (int nf = 0; nf < 8; nf++) {
                const int n = n0 + wn * 64 + nf * 8 + ((lane & 3) << 1);
                float2 v;
                v.x = acc[mf][nf][half * 2 + 0] + bias[n];
                v.y = acc[mf][nf][half * 2 + 1] + bias[n + 1];
                if (writeQKV) {
                    const int h = n >> 6;
                    const int d = n & 63;
                    *(float2*)(C + (((size_t)(b * NHEAD + h)) * SEQ + s) * HDIM + d) = v;
                } else {
                    *(float2*)(C + (size_t)m * EMB + n) = v;
                }
            }
        }
    }
}

// ===========================================================================
// Tensor-core causal flash attention.
// q-tile 128 (8 warps x 16 rows), k-tile 64, D=64. bf16 hi/lo split both
// matmuls (3 MMA terms each). K/V staged via smem (144B row stride:
// 16B-aligned + conflict-free); V fragments via ldmatrix.trans.
// ===========================================================================
#define QT 128
#define KT 64
#define AROWW 36            // u32 words per smem row (144 B)
#define ABUF (64 * AROWW)   // words per 64-row buffer

__global__ __launch_bounds__(256) void attn_tc(
    const float* __restrict__ Q, const float* __restrict__ K,
    const float* __restrict__ V, float* __restrict__ O)
{
    __shared__ uint32_t sm[4 * ABUF];   // 36864 B
    const int tid = threadIdx.x;
    const int lane = tid & 31;
    const int wid = tid >> 5;
    const int lr8 = lane & 7;
    const int mat = lane >> 3;
    const int qb = blockIdx.x;
    const int bh = blockIdx.y;

    const uint32_t sbase = smem_u32(sm);

    const float* Qg = Q + ((size_t)bh * SEQ + (size_t)qb * QT) * HDIM;
    const float* Kg = K + (size_t)bh * SEQ * HDIM;
    const float* Vg = V + (size_t)bh * SEQ * HDIM;

    const int r16 = tid >> 4;             // 0..15
    const int c4f = (tid & 15) << 2;      // 0..60 (float offset)
    const int kw  = (tid & 15) << 1;      // u32 word offset in row

    // ---- stage Q (x 1/8), split hi/lo into smem, ldsm into registers ----
#pragma unroll
    for (int u = 0; u < 8; u++) {
        const int row = r16 + u * 16;
        const float4 q = *(const float4*)(Qg + (size_t)row * HDIM + c4f);
        uint32_t h0, l0, h1, l1;
        split2(q.x * 0.125f, q.y * 0.125f, h0, l0);
        split2(q.z * 0.125f, q.w * 0.125f, h1, l1);
        const int w = row * AROWW + kw;
        *(uint2*)(sm + w) = make_uint2(h0, h1);             // Qh: bufs 0-1
        *(uint2*)(sm + 2 * ABUF + w) = make_uint2(l0, l1);  // Ql: bufs 2-3
    }
    __syncthreads();

    uint32_t qh[4][4], ql[4][4];
    {
        const uint32_t qa = sbase +
            (uint32_t)((wid * 16 + (mat & 1) * 8 + lr8) * 144 + (mat >> 1) * 16);
#pragma unroll
        for (int ks = 0; ks < 4; ks++) {
            ldsm4(qh[ks], qa + ks * 32);
            ldsm4(ql[ks], qa + 2 * ABUF * 4 + ks * 32);
        }
    }
    // top-of-loop sync protects Q smem reuse as K/V buffers

    float oacc[8][4];
#pragma unroll
    for (int nf = 0; nf < 8; nf++)
#pragma unroll
        for (int e = 0; e < 4; e++) oacc[nf][e] = 0.f;
    float m0r = -INFINITY, m1r = -INFINITY, l0r = 0.f, l1r = 0.f;

    const int jbmax = 2 * qb + 1;
    const int qrow0 = qb * QT + wid * 16 + (lane >> 2);

    // prefetch first K tile
    float4 kreg[4];
#pragma unroll
    for (int u = 0; u < 4; u++)
        kreg[u] = *(const float4*)(Kg + (size_t)(r16 + u * 16) * HDIM + c4f);

    for (int jb = 0; jb <= jbmax; jb++) {
        __syncthreads();    // prior tile's ldsm (K & V) complete in all warps
        // store K hi/lo (bufs 0-1)
#pragma unroll
        for (int u = 0; u < 4; u++) {
            uint32_t h0, l0, h1, l1;
            split2(kreg[u].x, kreg[u].y, h0, l0);
            split2(kreg[u].z, kreg[u].w, h1, l1);
            const int w = (r16 + u * 16) * AROWW + kw;
            *(uint2*)(sm + w) = make_uint2(h0, h1);
            *(uint2*)(sm + ABUF + w) = make_uint2(l0, l1);
        }
        __syncthreads();

        // prefetch V tile (overlaps S-MMA)
        float4 vreg[4];
        {
            const float* Vt = Vg + (size_t)jb * KT * HDIM;
#pragma unroll
            for (int u = 0; u < 4; u++)
                vreg[u] = *(const float4*)(Vt + (size_t)(r16 + u * 16) * HDIM + c4f);
        }

        // S = Q K^T (3-term split)
        float sacc[8][4];
#pragma unroll
        for (int nf = 0; nf < 8; nf++)
#pragma unroll
            for (int e = 0; e < 4; e++) sacc[nf][e] = 0.f;

#pragma unroll
        for (int ks = 0; ks < 4; ks++) {
#pragma unroll
            for (int np = 0; np < 4; np++) {
                uint32_t kh[4], kl[4];
                const uint32_t ka = sbase +
                    (uint32_t)((np * 16 + (mat >> 1) * 8 + lr8) * 144 + ks * 32 + (mat & 1) * 16);
                ldsm4(kh, ka);
                ldsm4(kl, ka + ABUF * 4);
#pragma unroll
                for (int hh = 0; hh < 2; hh++) {
                    float* d = sacc[np * 2 + hh];
                    mma_bf16(d, qh[ks], &kh[hh * 2]);
                    mma_bf16(d, qh[ks], &kl[hh * 2]);
                    mma_bf16(d, ql[ks], &kh[hh * 2]);
                }
            }
        }

        // store V hi/lo (bufs 2-3; prior readers done before top sync)
#pragma unroll
        for (int u = 0; u < 4; u++) {
            uint32_t h0, l0, h1, l1;
            split2(vreg[u].x, vreg[u].y, h0, l0);
            split2(vreg[u].z, vreg[u].w, h1, l1);
            const int w = (r16 + u * 16) * AROWW + kw;
            *(uint2*)(sm + 2 * ABUF + w) = make_uint2(h0, h1);
            *(uint2*)(sm + 3 * ABUF + w) = make_uint2(l0, l1);
        }
        __syncthreads();

        // prefetch next K tile (overlaps softmax + PV)
        if (jb < jbmax) {
            const float* Kt = Kg + (size_t)(jb + 1) * KT * HDIM;
#pragma unroll
            for (int u = 0; u < 4; u++)
                kreg[u] = *(const float4*)(Kt + (size_t)(r16 + u * 16) * HDIM + c4f);
        }

        // causal mask (diagonal-band tiles only)
        if (jb * KT + KT - 1 > qrow0) {
#pragma unroll
            for (int nt = 0; nt < 8; nt++) {
                const int c = jb * KT + nt * 8 + ((lane & 3) << 1);
                if (c     > qrow0)     sacc[nt][0] = -INFINITY;
                if (c + 1 > qrow0)     sacc[nt][1] = -INFINITY;
                if (c     > qrow0 + 8) sacc[nt][2] = -INFINITY;
                if (c + 1 > qrow0 + 8) sacc[nt][3] = -INFINITY;
            }
        }

        // online softmax over fragments (rows r, r+8; reduce across 4 lanes)
        float mx0 = sacc[0][0], mx1 = sacc[0][2];
#pragma unroll
        for (int nt = 0; nt < 8; nt++) {
            mx0 = fmaxf(mx0, fmaxf(sacc[nt][0], sacc[nt][1]));
            mx1 = fmaxf(mx1, fmaxf(sacc[nt][2], sacc[nt][3]));
        }
        mx0 = fmaxf(mx0, __shfl_xor_sync(~0u, mx0, 1));
        mx0 = fmaxf(mx0, __shfl_xor_sync(~0u, mx0, 2));
        mx1 = fmaxf(mx1, __shfl_xor_sync(~0u, mx1, 1));
        mx1 = fmaxf(mx1, __shfl_xor_sync(~0u, mx1, 2));
        const float mn0 = fmaxf(m0r, mx0), mn1 = fmaxf(m1r, mx1);
        const float cr0 = __expf(m0r - mn0), cr1 = __expf(m1r - mn1);
        m0r = mn0; m1r = mn1;
        float rs0 = 0.f, rs1 = 0.f;
#pragma unroll
        for (int nt = 0; nt < 8; nt++) {
            sacc[nt][0] = __expf(sacc[nt][0] - mn0);
            sacc[nt][1] = __expf(sacc[nt][1] - mn0);
            sacc[nt][2] = __expf(sacc[nt][2] - mn1);
            sacc[nt][3] = __expf(sacc[nt][3] - mn1);
            rs0 += sacc[nt][0] + sacc[nt][1];
            rs1 += sacc[nt][2] + sacc[nt][3];
        }
        rs0 += __shfl_xor_sync(~0u, rs0, 1);
        rs0 += __shfl_xor_sync(~0u, rs0, 2);
        rs1 += __shfl_xor_sync(~0u, rs1, 1);
        rs1 += __shfl_xor_sync(~0u, rs1, 2);
        l0r = l0r * cr0 + rs0;
        l1r = l1r * cr1 + rs1;
#pragma unroll
        for (int nf = 0; nf < 8; nf++) {
            oacc[nf][0] *= cr0; oacc[nf][1] *= cr0;
            oacc[nf][2] *= cr1; oacc[nf][3] *= cr1;
        }

        // O += P V (3-term split); P fragments built in registers from sacc
#pragma unroll
        for (int ks = 0; ks < 4; ks++) {
            uint32_t ph[4], pl[4];
            split2(sacc[2 * ks][0],     sacc[2 * ks][1],     ph[0], pl[0]);
            split2(sacc[2 * ks][2],     sacc[2 * ks][3],     ph[1], pl[1]);
            split2(sacc[2 * ks + 1][0], sacc[2 * ks + 1][1], ph[2], pl[2]);
            split2(sacc[2 * ks + 1][2], sacc[2 * ks + 1][3], ph[3], pl[3]);
#pragma unroll
            for (int np = 0; np < 4; np++) {
                uint32_t vh[4], vl[4];
                const uint32_t va = sbase + (uint32_t)(2 * ABUF * 4) +
                    (uint32_t)((ks * 16 + (mat & 1) * 8 + lr8) * 144 + np * 32 + (mat >> 1) * 16);
                ldsm4t(vh, va);
                ldsm4t(vl, va + ABUF * 4);
#pragma unroll
                for (int hh = 0; hh < 2; hh++) {
                    float* d = oacc[np * 2 + hh];
                    mma_bf16(d, ph, &vh[hh * 2]);
                    mma_bf16(d, ph, &vl[hh * 2]);
                    mma_bf16(d, pl, &vh[hh * 2]);
                }
            }
        }
    }

    // epilogue: normalize, write [b, s, h*64 + d]
    const int b = bh >> 4, h = bh & 15;
    const float inv0 = 1.f / l0r, inv1 = 1.f / l1r;
#pragma unroll
    for (int nt = 0; nt < 8; nt++) {
        const int col = h * HDIM + nt * 8 + ((lane & 3) << 1);
        *(float2*)(O + ((size_t)(b * SEQ) + qrow0) * EMB + col) =
            make_float2(oacc[nt][0] * inv0, oacc[nt][1] * inv0);
        *(float2*)(O + ((size_t)(b * SEQ) + qrow0 + 8) * EMB + col) =
            make_float2(oacc[nt][2] * inv1, oacc[nt][3] * inv1);
    }
}

// ---------------------------------------------------------------------------
extern "C" void kernel_launch(void* const* d_in, const int* in_sizes, int n_in,
                              void* d_out, int out_size)
{
    (void)in_sizes; (void)n_in; (void)out_size;
    const float* x  = (const float*)d_in[0];
    // d_in[1] = mask (causal tril, implied — unused)
    const float* Wq = (const float*)d_in[2];
    const float* bq = (const float*)d_in[3];
    const float* Wk = (const float*)d_in[4];
    const float* bk = (const float*)d_in[5];
    const float* Wv = (const float*)d_in[6];
    const float* bv = (const float*)d_in[7];
    const float* Wo = (const float*)d_in[8];
    const float* bo = (const float*)d_in[9];
    float* out = (float*)d_out;

    float *gq, *gk, *gv, *go;
    cudaGetSymbolAddress((void**)&gq, g_q);
    cudaGetSymbolAddress((void**)&gk, g_k);
    cudaGetSymbolAddress((void**)&gv, g_v);
    cudaGetSymbolAddress((void**)&go, g_o);

    const dim3 gemm_grid(EMB / 128, MTOT / 128);  // (8, 32)
    gemm_tc<<<gemm_grid, 256>>>(x, Wq, bq, gq, 1);
    gemm_tc<<<gemm_grid, 256>>>(x, Wk, bk, gk, 1);
    gemm_tc<<<gemm_grid, 256>>>(x, Wv, bv, gv, 1);

    const dim3 attn_grid(SEQ / QT, BATCH * NHEAD);  // (16, 32)
    attn_tc<<<attn_grid, 256>>>(gq, gk, gv, go);

    gemm_tc<<<gemm_grid, 256>>>(go, Wo, bo, out, 0);
}